// round 9
// baseline (speedup 1.0000x reference)
#include <cuda_runtime.h>
#include <cuda_bf16.h>
#include <cstdint>

#define NUM_TOKENS 131072
#define NUM_EXPERTS 256
#define TOPK 8
#define LOG2E 1.4426950408889634f

__device__ __forceinline__ float ex2(float x) {
    float y; asm("ex2.approx.ftz.f32 %0, %1;" : "=f"(y) : "f"(x)); return y;
}

__global__ void __launch_bounds__(256, 4)
moe_topk_softmax_kernel(const float* __restrict__ gating,
                        float* __restrict__ out) {
    __shared__ float sv[8][72];   // survivor values (+padding slots)
    __shared__ int   si[8][64];   // survivor expert indices
    const int wib  = threadIdx.x >> 5;
    const int lane = threadIdx.x & 31;
    const int warp = blockIdx.x * 8 + wib;
    const float NEG_INF = __int_as_float(0xff800000);

    // Coalesced row load: 64 float4 per row
    const float4* row = reinterpret_cast<const float4*>(gating + (size_t)warp * NUM_EXPERTS);
    float4 A = __ldg(&row[lane]);
    float4 B = __ldg(&row[lane + 32]);
    float v[8] = {A.x, A.y, A.z, A.w, B.x, B.y, B.z, B.w};

    // Per-lane max
    float lm = v[0];
#pragma unroll
    for (int j = 1; j < 8; j++) lm = fmaxf(lm, v[j]);

    // Quad max (32 disjoint elements per lane-quad); then
    // thr = min of the 8 quad-maxima (8 distinct elements => thr <= t8, prune-safe)
    // rmax = row max (for softmax), computed on the same tree.
    float qm = fmaxf(lm, __shfl_xor_sync(0xffffffffu, lm, 1));
    qm = fmaxf(qm, __shfl_xor_sync(0xffffffffu, qm, 2));
    float thr = qm, rmax = qm;
#pragma unroll
    for (int o = 4; o < 32; o <<= 1) {
        float t = __shfl_xor_sync(0xffffffffu, thr, o);
        float m = __shfl_xor_sync(0xffffffffu, rmax, o);
        thr  = fminf(thr, t);
        rmax = fmaxf(rmax, m);
    }

    // Flags + exclusive prefix scan of survivor counts
    bool f[8];
    int c, off, S;
#define SCAN_FLAGS(T)                                                      \
    {                                                                      \
        c = 0;                                                             \
        _Pragma("unroll")                                                  \
        for (int j = 0; j < 8; j++) { f[j] = (v[j] >= (T)); c += f[j]; }   \
        off = c;                                                           \
        _Pragma("unroll")                                                  \
        for (int d = 1; d < 32; d <<= 1) {                                 \
            int t_ = __shfl_up_sync(0xffffffffu, off, d);                  \
            if (lane >= d) off += t_;                                      \
        }                                                                  \
        S = __shfl_sync(0xffffffffu, off, 31);                             \
        off -= c;                                                          \
    }
    SCAN_FLAGS(thr);

    // Rare (~0.3%) fallback: exact 8th-largest of the 32 lane maxima
    // (bounds survivors <= ~57 < 64).
    if (S > 64) {
        float s = lm;
#pragma unroll
        for (int k = 2; k <= 32; k <<= 1) {
#pragma unroll
            for (int j = k >> 1; j > 0; j >>= 1) {
                float o = __shfl_xor_sync(0xffffffffu, s, j);
                bool up    = ((lane & k) == 0);
                bool lower = ((lane & j) == 0);
                s = (lower == up) ? fminf(s, o) : fmaxf(s, o);
            }
        }
        float m8f = __shfl_sync(0xffffffffu, s, 24);
        SCAN_FLAGS(m8f);
    }
#undef SCAN_FLAGS
    const int Sc = (S < 64) ? S : 64;   // memory-safety clamp (never binds on gaussian data)

    // Compact survivors (value + index) into shared memory
    float* WV = sv[wib];
    int*   WI = si[wib];
    const int base = lane * 4;
#pragma unroll
    for (int j = 0; j < 8; j++) {
        if (f[j]) {
            int g = (j < 4) ? (base + j) : (124 + base + j);   // 128 + base + (j-4)
            if (off < 64) { WV[off] = v[j]; WI[off] = g; }
            off++;
        }
    }
    if (lane < 4) WV[Sc + lane] = NEG_INF;   // padding for 4-wide loop (Sc+3 <= 67 < 72)
    __syncwarp();

    // Each lane ranks survivor slot `lane` (and `lane+32` when S>32) by counting
    // strictly-greater values (broadcast LDS, conflict-free, fully parallel).
    float me1v = NEG_INF, me2v = NEG_INF;
    int   me1g = 0,       me2g = 0;
    if (lane < Sc) { me1v = WV[lane]; me1g = WI[lane]; }
    int r1 = 99, r2 = 99;
    const int Sp = (Sc + 3) & ~3;
    if (Sc <= 32) {
        int rk = 0;
        for (int i = 0; i < Sp; i += 4) {
            float e0 = WV[i], e1 = WV[i+1], e2 = WV[i+2], e3 = WV[i+3];
            rk += (e0 > me1v) + (e1 > me1v) + (e2 > me1v) + (e3 > me1v);
        }
        if (lane < Sc) r1 = rk;
    } else {
        if (lane + 32 < Sc) { me2v = WV[lane + 32]; me2g = WI[lane + 32]; }
        int ra = 0, rb = 0;
        for (int i = 0; i < Sp; i += 4) {
            float e0 = WV[i], e1 = WV[i+1], e2 = WV[i+2], e3 = WV[i+3];
            ra += (e0 > me1v) + (e1 > me1v) + (e2 > me1v) + (e3 > me1v);
            rb += (e0 > me2v) + (e1 > me2v) + (e2 > me2v) + (e3 > me2v);
        }
        if (lane < Sc)      r1 = ra;
        if (lane + 32 < Sc) r2 = rb;
    }

    // Exactness check: winners must cover ranks 0..7 exactly once.
    // Any value-tie corruption breaks (mask==0xFF && count==8).
    unsigned wbit = ((r1 < 8) ? (1u << r1) : 0u) | ((r2 < 8) ? (1u << r2) : 0u);
    unsigned cnt  = (unsigned)(r1 < 8) + (unsigned)(r2 < 8);
    unsigned mask = __reduce_or_sync(0xffffffffu, wbit);
    unsigned tot  = __reduce_add_sync(0xffffffffu, cnt);
    if (!(mask == 0xFFu && tot == 8u)) {
        // Tie-aware exact ranking (value desc, index asc) — matches jax.lax.top_k.
        int ra = 0, rb = 0;
        for (int i = 0; i < Sc; i++) {
            float ev = WV[i]; int eg = WI[i];
            ra += (ev > me1v) || (ev == me1v && eg < me1g);
            rb += (ev > me2v) || (ev == me2v && eg < me2g);
        }
        r1 = (lane < Sc)      ? ra : 99;
        r2 = (lane + 32 < Sc) ? rb : 99;
    }

    // Softmax denominator over all 256 (independent of selection)
    const float rm2 = rmax * LOG2E;
    float sm = 0.f;
#pragma unroll
    for (int j = 0; j < 8; j++) sm += ex2(fmaf(v[j], LOG2E, -rm2));
#pragma unroll
    for (int o2 = 16; o2 > 0; o2 >>= 1) sm += __shfl_xor_sync(0xffffffffu, sm, o2);
    const float inv = __fdividef(1.0f, sm);

    // Winners write their own slot directly.
    // Layout: [weights (TOKENS*8) | indices-as-float (TOKENS*8)]
    float* wbase = out + (size_t)warp * TOPK;
    float* ibase = out + (size_t)NUM_TOKENS * TOPK + (size_t)warp * TOPK;
    if (r1 < 8) {
        wbase[r1] = ex2(fmaf(me1v, LOG2E, -rm2)) * inv;
        ibase[r1] = (float)me1g;
    }
    if (r2 < 8) {
        wbase[r2] = ex2(fmaf(me2v, LOG2E, -rm2)) * inv;
        ibase[r2] = (float)me2g;
    }
}

extern "C" void kernel_launch(void* const* d_in, const int* in_sizes, int n_in,
                              void* d_out, int out_size) {
    const float* gating = (const float*)d_in[0];
    float* out = (float*)d_out;
    const int blocks = NUM_TOKENS / 8;   // 8 warps (tokens) per 256-thread block
    moe_topk_softmax_kernel<<<blocks, 256>>>(gating, out);
}

// round 11
// speedup vs baseline: 1.0770x; 1.0770x over previous
#include <cuda_runtime.h>
#include <cuda_bf16.h>
#include <cstdint>

#define NUM_TOKENS 131072
#define NUM_EXPERTS 256
#define TOPK 8
#define LOG2E 1.4426950408889634f

__device__ __forceinline__ float ex2(float x) {
    float y; asm("ex2.approx.ftz.f32 %0, %1;" : "=f"(y) : "f"(x)); return y;
}

__global__ void __launch_bounds__(256, 6)
moe_topk_softmax_kernel(const float* __restrict__ gating,
                        float* __restrict__ out) {
    __shared__ __align__(16) float sv[8][72];   // survivor values (+pad); 288B rows keep 16B alignment
    __shared__ int   si[8][64];                 // survivor expert indices
    const int wib  = threadIdx.x >> 5;
    const int lane = threadIdx.x & 31;
    const int warp = blockIdx.x * 8 + wib;
    const float NEG_INF = __int_as_float(0xff800000);

    // Coalesced row load: 64 float4 per row
    const float4* row = reinterpret_cast<const float4*>(gating + (size_t)warp * NUM_EXPERTS);
    float4 A = __ldg(&row[lane]);
    float4 B = __ldg(&row[lane + 32]);
    float v[8] = {A.x, A.y, A.z, A.w, B.x, B.y, B.z, B.w};

    // Per-lane max
    float lm = v[0];
#pragma unroll
    for (int j = 1; j < 8; j++) lm = fmaxf(lm, v[j]);

    // Quad max (32 disjoint elems per lane-quad); thr = min of the 8 quad-maxima
    // (8 distinct elements => thr <= t8, prune provably keeps top-8). rmax = row max.
    float qm = fmaxf(lm, __shfl_xor_sync(0xffffffffu, lm, 1));
    qm = fmaxf(qm, __shfl_xor_sync(0xffffffffu, qm, 2));
    float thr = qm, rmax = qm;
#pragma unroll
    for (int o = 4; o < 32; o <<= 1) {
        float t = __shfl_xor_sync(0xffffffffu, thr, o);
        float m = __shfl_xor_sync(0xffffffffu, rmax, o);
        thr  = fminf(thr, t);
        rmax = fmaxf(rmax, m);
    }

    // ---- Softmax denominator EARLY (shortens v's live range; overlaps MUFU) ----
    const float rm2 = rmax * LOG2E;
    float sm = 0.f;
#pragma unroll
    for (int j = 0; j < 8; j++) sm += ex2(fmaf(v[j], LOG2E, -rm2));
#pragma unroll
    for (int o2 = 16; o2 > 0; o2 >>= 1) sm += __shfl_xor_sync(0xffffffffu, sm, o2);
    const float inv = __fdividef(1.0f, sm);

    // ---- Flag mask + exclusive prefix scan of survivor counts ----
    unsigned bm;
    int c, off, S;
#define SCAN_FLAGS(T)                                                      \
    {                                                                      \
        bm = 0u;                                                           \
        _Pragma("unroll")                                                  \
        for (int j = 0; j < 8; j++) bm |= (v[j] >= (T)) ? (1u << j) : 0u;  \
        c = __popc(bm);                                                    \
        off = c;                                                           \
        _Pragma("unroll")                                                  \
        for (int d = 1; d < 32; d <<= 1) {                                 \
            int t_ = __shfl_up_sync(0xffffffffu, off, d);                  \
            if (lane >= d) off += t_;                                      \
        }                                                                  \
        S = __shfl_sync(0xffffffffu, off, 31);                             \
        off -= c;                                                          \
    }
    SCAN_FLAGS(thr);

    // Rare (~0.3%) fallback: exact 8th-largest of the 32 lane maxima (bounds S <= ~57)
    if (S > 64) {
        float s = lm;
#pragma unroll
        for (int k = 2; k <= 32; k <<= 1) {
#pragma unroll
            for (int j = k >> 1; j > 0; j >>= 1) {
                float o = __shfl_xor_sync(0xffffffffu, s, j);
                bool up    = ((lane & k) == 0);
                bool lower = ((lane & j) == 0);
                s = (lower == up) ? fminf(s, o) : fmaxf(s, o);
            }
        }
        float m8f = __shfl_sync(0xffffffffu, s, 24);
        SCAN_FLAGS(m8f);
    }
#undef SCAN_FLAGS
    const int Sc = (S < 64) ? S : 64;   // memory-safety clamp (never binds on gaussian data)

    // ---- Compact survivors (value + index) into shared memory; v dies here ----
    float* WV = sv[wib];
    int*   WI = si[wib];
    const int base = lane * 4;
#pragma unroll
    for (int j = 0; j < 8; j++) {
        if (bm & (1u << j)) {
            int g = (j < 4) ? (base + j) : (124 + base + j);   // 128 + base + (j-4)
            if (off < 64) { WV[off] = v[j]; WI[off] = g; }
            off++;
        }
    }
    if (lane < 4) WV[Sc + lane] = NEG_INF;   // pad for float4 loop (Sc+3 <= 67 < 72)
    __syncwarp();

    // ---- Rank survivor slot `lane` (and `lane+32` if S>32) by counting greater values.
    // Broadcast LDS.128, conflict-free, fully parallel.
    const float4* WV4 = reinterpret_cast<const float4*>(WV);
    float me1v = NEG_INF, me2v = NEG_INF;
    int   me1g = 0,       me2g = 0;
    if (lane < Sc) { me1v = WV[lane]; me1g = WI[lane]; }
    int r1 = 99, r2 = 99;
    const int nIter = (Sc + 3) >> 2;
    if (Sc <= 32) {
        int rk = 0;
        for (int i = 0; i < nIter; i++) {
            float4 e = WV4[i];
            rk += (e.x > me1v) + (e.y > me1v) + (e.z > me1v) + (e.w > me1v);
        }
        if (lane < Sc) r1 = rk;
    } else {
        if (lane + 32 < Sc) { me2v = WV[lane + 32]; me2g = WI[lane + 32]; }
        int ra = 0, rb = 0;
        for (int i = 0; i < nIter; i++) {
            float4 e = WV4[i];
            ra += (e.x > me1v) + (e.y > me1v) + (e.z > me1v) + (e.w > me1v);
            rb += (e.x > me2v) + (e.y > me2v) + (e.z > me2v) + (e.w > me2v);
        }
        if (lane < Sc)      r1 = ra;
        if (lane + 32 < Sc) r2 = rb;
    }

    // ---- Exactness check: winners must cover ranks 0..7 exactly once ----
    unsigned wbit = ((r1 < 8) ? (1u << r1) : 0u) | ((r2 < 8) ? (1u << r2) : 0u);
    unsigned cnt  = (unsigned)(r1 < 8) + (unsigned)(r2 < 8);
    unsigned mask = __reduce_or_sync(0xffffffffu, wbit);
    unsigned tot  = __reduce_add_sync(0xffffffffu, cnt);
    if (!(mask == 0xFFu && tot == 8u)) {
        // Tie-aware exact ranking (value desc, index asc) — matches jax.lax.top_k.
        int ra = 0, rb = 0;
        for (int i = 0; i < Sc; i++) {
            float ev = WV[i]; int eg = WI[i];
            ra += (ev > me1v) || (ev == me1v && eg < me1g);
            rb += (ev > me2v) || (ev == me2v && eg < me2g);
        }
        r1 = (lane < Sc)      ? ra : 99;
        r2 = (lane + 32 < Sc) ? rb : 99;
    }

    // ---- Winners write their own slot directly ----
    // Layout: [weights (TOKENS*8) | indices-as-float (TOKENS*8)]
    float* wbase = out + (size_t)warp * TOPK;
    float* ibase = out + (size_t)NUM_TOKENS * TOPK + (size_t)warp * TOPK;
    if (r1 < 8) {
        wbase[r1] = ex2(fmaf(me1v, LOG2E, -rm2)) * inv;
        ibase[r1] = (float)me1g;
    }
    if (r2 < 8) {
        wbase[r2] = ex2(fmaf(me2v, LOG2E, -rm2)) * inv;
        ibase[r2] = (float)me2g;
    }
}

extern "C" void kernel_launch(void* const* d_in, const int* in_sizes, int n_in,
                              void* d_out, int out_size) {
    const float* gating = (const float*)d_in[0];
    float* out = (float*)d_out;
    const int blocks = NUM_TOKENS / 8;   // 8 warps (tokens) per 256-thread block
    moe_topk_softmax_kernel<<<blocks, 256>>>(gating, out);
}